// round 11
// baseline (speedup 1.0000x reference)
#include <cuda_runtime.h>
#include <cuda_bf16.h>
#include <cstdint>

// Problem constants
#define NTOK   8192
#define DMODEL 4096
#define DSAE   16384
#define KSP    64

#define BAND_EPS 2e-4f   // boundary-ambiguity band on pre_act value scale

// d_out layout: [recon (NTOK*DMODEL) | sparse (NTOK*DSAE) | pre (NTOK*DSAE)]

// ---------------- scratch (__device__ globals) ----------------
__device__ float g_WdecT[(size_t)DSAE * DMODEL];   // 256 MB transposed decoder weights
__device__ int   g_topidx[(size_t)NTOK * KSP];
__device__ float g_topval[(size_t)NTOK * KSP];
__device__ float g_vT[NTOK];
__device__ int   g_flag[NTOK];
// bf16 split operands for tensor-core encoder
__device__ __nv_bfloat16 g_Ahi[(size_t)NTOK * DMODEL];   // 64 MB
__device__ __nv_bfloat16 g_Amid[(size_t)NTOK * DMODEL];  // 64 MB
__device__ __nv_bfloat16 g_Bhi[(size_t)DSAE * DMODEL];   // 128 MB
__device__ __nv_bfloat16 g_Bmid[(size_t)DSAE * DMODEL];  // 128 MB

// ---------------- baseline-PTX helpers (sm_80-level only; NO _a features) -----
__device__ __forceinline__ uint32_t smem_to_u32(const void* p) {
    uint32_t a;
    asm("{ .reg .u64 t; cvta.to.shared.u64 t, %1; cvt.u32.u64 %0, t; }"
        : "=r"(a) : "l"(p));
    return a;
}
__device__ __forceinline__ void cp_async16(uint32_t saddr, const void* gaddr) {
    asm volatile("cp.async.cg.shared.global [%0], [%1], 16;" :: "r"(saddr), "l"(gaddr));
}
#define CP_COMMIT() asm volatile("cp.async.commit_group;" ::: "memory")
template <int N>
__device__ __forceinline__ void cp_wait_group() {
    asm volatile("cp.async.wait_group %0;" :: "n"(N) : "memory");
}

// mma.sync m16n8k16 row.col bf16 -> f32 (PTX ISA 7.0, baseline sm_80)
__device__ __forceinline__ void mma16816(float* d, const uint32_t* a, const uint32_t* b) {
    asm volatile(
        "mma.sync.aligned.m16n8k16.row.col.f32.bf16.bf16.f32 "
        "{%0,%1,%2,%3}, {%4,%5,%6,%7}, {%8,%9}, {%0,%1,%2,%3};"
        : "+f"(d[0]), "+f"(d[1]), "+f"(d[2]), "+f"(d[3])
        : "r"(a[0]), "r"(a[1]), "r"(a[2]), "r"(a[3]), "r"(b[0]), "r"(b[1]));
}

// ldmatrix x4 (baseline PTX since sm_75) — 4x fewer load issues than LDS.32
__device__ __forceinline__ void ldsm4(uint32_t* r, uint32_t addr) {
    asm volatile("ldmatrix.sync.aligned.m8n8.x4.shared.b16 {%0,%1,%2,%3}, [%4];"
        : "=r"(r[0]), "=r"(r[1]), "=r"(r[2]), "=r"(r[3]) : "r"(addr));
}

// =====================================================================
// Kernel 0: bf16 two-way split, vectorized (float4 in, bf16x2 packed out)
// =====================================================================
__global__ __launch_bounds__(256)
void split_pair(const float4* __restrict__ src, uint2* __restrict__ hi,
                uint2* __restrict__ mid, size_t n4)
{
    size_t i = (size_t)blockIdx.x * 256 + threadIdx.x;
    size_t stride = (size_t)gridDim.x * 256;
    for (; i < n4; i += stride) {
        float4 v = src[i];
        __nv_bfloat162 h01 = __float22bfloat162_rn(make_float2(v.x, v.y));
        __nv_bfloat162 h23 = __float22bfloat162_rn(make_float2(v.z, v.w));
        float2 hf01 = __bfloat1622float2(h01);
        float2 hf23 = __bfloat1622float2(h23);
        __nv_bfloat162 m01 = __float22bfloat162_rn(make_float2(v.x - hf01.x, v.y - hf01.y));
        __nv_bfloat162 m23 = __float22bfloat162_rn(make_float2(v.z - hf23.x, v.w - hf23.y));
        hi[i]  = make_uint2(*(uint32_t*)&h01, *(uint32_t*)&h23);
        mid[i] = make_uint2(*(uint32_t*)&m01, *(uint32_t*)&m23);
    }
}

// =====================================================================
// Kernel 1: HMMA encoder GEMM (bf16x3 split):
//   pre = Ahi·Bhi^T + Ahi·Bmid^T + Amid·Bhi^T + bias  (fp32 accum)
// CTA tile 128x256, BK=32, 3-stage cp.async pipeline, 256 threads,
// 64x64 warp tiles, fragments via ldmatrix.x4 (conflict-free @80B stride).
// MMA issue order identical to R10 -> bitwise-identical pre_acts.
// =====================================================================
#define HB_BM 128
#define HB_BN 256
#define HB_BK 32
#define HB_RSB 80                        // 64B data (32 bf16) + 16B pad
#define HB_A_MAT (128 * HB_RSB)          // 10240 B
#define HB_B_MAT (256 * HB_RSB)          // 20480 B
#define HB_STAGE (2 * HB_A_MAT + 2 * HB_B_MAT)   // 61440 B
#define HB_NSTAGE 3
#define HB_SMEM (HB_NSTAGE * HB_STAGE)   // 184320 B
#define OFF_AHI  0
#define OFF_AMID HB_A_MAT
#define OFF_BHI  (2 * HB_A_MAT)
#define OFF_BMID (2 * HB_A_MAT + HB_B_MAT)

__global__ __launch_bounds__(256, 1)
void enc_hmma(const float* __restrict__ bias, float* __restrict__ C)
{
    extern __shared__ char smem[];
    const int tid  = threadIdx.x;
    const int wid  = tid >> 5;
    const int lane = tid & 31;

    // rasterize: groups of 8 M-tiles x all 64 N-tiles (A slice L2-resident)
    const int t  = blockIdx.x;
    const int g  = t >> 9;              // /(8*64)
    const int r  = t & 511;
    const int mt = (g << 3) + (r & 7);
    const int nt = r >> 3;
    const int m0 = mt * HB_BM;
    const int n0 = nt * HB_BN;

    const int warp_m = (wid >> 2) * 64;   // 0 / 64
    const int warp_n = (wid & 3) * 64;    // 0..192

    float acc[4][8][4];
#pragma unroll
    for (int i = 0; i < 4; i++)
#pragma unroll
        for (int j = 0; j < 8; j++)
#pragma unroll
            for (int q = 0; q < 4; q++) acc[i][j][q] = 0.0f;

    const uint32_t sb = smem_to_u32(smem);
    const int NCH = DMODEL / HB_BK;      // 128

    // ---- per-thread loader plan: 12 x 16B chunks per stage (3072 total) ----
    uint32_t soff[12];
    const char* gptr[12];
    {
        const char* gAhi  = (const char*)g_Ahi  + (size_t)m0 * DMODEL * 2;
        const char* gAmid = (const char*)g_Amid + (size_t)m0 * DMODEL * 2;
        const char* gBhi  = (const char*)g_Bhi  + (size_t)n0 * DMODEL * 2;
        const char* gBmid = (const char*)g_Bmid + (size_t)n0 * DMODEL * 2;
#pragma unroll
        for (int i = 0; i < 12; i++) {
            int c = tid + i * 256;
            if (c < 1024) {                       // A chunks: 2 mats x 128 rows x 4
                int mat = c >> 9;
                int row = (c >> 2) & 127;
                int col = c & 3;
                soff[i] = (mat ? OFF_AMID : OFF_AHI) + row * HB_RSB + col * 16;
                gptr[i] = (mat ? gAmid : gAhi) + (size_t)row * (DMODEL * 2) + col * 16;
            } else {                              // B chunks: 2 mats x 256 rows x 4
                int cb  = c - 1024;
                int mat = cb >> 10;
                int row = (cb >> 2) & 255;
                int col = cb & 3;
                soff[i] = (mat ? OFF_BMID : OFF_BHI) + row * HB_RSB + col * 16;
                gptr[i] = (mat ? gBmid : gBhi) + (size_t)row * (DMODEL * 2) + col * 16;
            }
        }
    }

    auto load_stage = [&](int ch, int s) {
        const uint32_t stg = sb + s * HB_STAGE;
        const size_t kadv = (size_t)ch * 64;     // 32 bf16 = 64 bytes per chunk
#pragma unroll
        for (int i = 0; i < 12; i++)
            cp_async16(stg + soff[i], gptr[i] + kadv);
        CP_COMMIT();
    };

    load_stage(0, 0);
    load_stage(1, 1);

    // ldmatrix lane offset: thread t -> matrix t>>3; row = (t&7) + 8*((t>>3)&1),
    // k-half = 16B * (t>>4). Covers m0..m3 of a 16x16 bf16 tile.
    const uint32_t laneoff =
        (uint32_t)(((lane & 7) + ((lane >> 3) & 1) * 8) * HB_RSB + ((lane >> 4) & 1) * 16);

    const int gg = lane >> 2;
    const int tg = lane & 3;

    for (int ch = 0; ch < NCH; ch++) {
        if (ch + 1 < NCH) cp_wait_group<1>();
        else              cp_wait_group<0>();
        __syncthreads();

        if (ch + 2 < NCH) load_stage(ch + 2, (ch + 2) % 3);

        const uint32_t stgu = sb + (ch % 3) * HB_STAGE;

#pragma unroll
        for (int ks = 0; ks < 2; ks++) {
            const int kb = ks * 32;              // 16 bf16 = 32B per k-step
            uint32_t ah[4][4], am[4][4];
            const uint32_t abase = stgu + (uint32_t)(warp_m * HB_RSB + kb) + laneoff;
#pragma unroll
            for (int i = 0; i < 4; i++) {
                ldsm4(ah[i], abase + OFF_AHI  + i * (16 * HB_RSB));
                ldsm4(am[i], abase + OFF_AMID + i * (16 * HB_RSB));
            }
            const uint32_t bbase = stgu + (uint32_t)(warp_n * HB_RSB + kb) + laneoff;
#pragma unroll
            for (int jp = 0; jp < 4; jp++) {
                uint32_t bh4[4], bm4[4];
                ldsm4(bh4, bbase + OFF_BHI  + jp * (16 * HB_RSB));
                ldsm4(bm4, bbase + OFF_BMID + jp * (16 * HB_RSB));
                // x4 gives two j-tiles: regs {0,2} -> j=2jp, {1,3} -> j=2jp+1
                uint32_t bh0[2] = {bh4[0], bh4[2]}, bh1[2] = {bh4[1], bh4[3]};
                uint32_t bm0[2] = {bm4[0], bm4[2]}, bm1[2] = {bm4[1], bm4[3]};
#pragma unroll
                for (int i = 0; i < 4; i++) {
                    mma16816(acc[i][2 * jp], ah[i], bh0);
                    mma16816(acc[i][2 * jp], ah[i], bm0);
                    mma16816(acc[i][2 * jp], am[i], bh0);
                }
#pragma unroll
                for (int i = 0; i < 4; i++) {
                    mma16816(acc[i][2 * jp + 1], ah[i], bh1);
                    mma16816(acc[i][2 * jp + 1], ah[i], bm1);
                    mma16816(acc[i][2 * jp + 1], am[i], bh1);
                }
            }
        }
    }

    // ---- epilogue: bias add + store ----
#pragma unroll
    for (int i = 0; i < 4; i++) {
        const int row0 = m0 + warp_m + i * 16 + gg;
#pragma unroll
        for (int j = 0; j < 8; j++) {
            const int col = n0 + warp_n + j * 8 + tg * 2;
            const float b0 = bias[col];
            const float b1 = bias[col + 1];
            float* p0 = C + (size_t)row0 * DSAE + col;
            float* p1 = C + (size_t)(row0 + 8) * DSAE + col;
            *(float2*)p0 = make_float2(acc[i][j][0] + b0, acc[i][j][1] + b1);
            *(float2*)p1 = make_float2(acc[i][j][2] + b0, acc[i][j][3] + b1);
        }
    }
}

// =====================================================================
// Kernel 2: transpose W_dec (DMODEL x DSAE) -> g_WdecT (DSAE x DMODEL)
// =====================================================================
__global__ __launch_bounds__(256)
void wdec_transpose(const float* __restrict__ W)
{
    __shared__ float s[32][33];
    const int f0 = blockIdx.x * 32;
    const int d0 = blockIdx.y * 32;
    const int tx = threadIdx.x;
    const int ty = threadIdx.y;
#pragma unroll
    for (int j = 0; j < 32; j += 8)
        s[ty + j][tx] = W[(size_t)(d0 + ty + j) * DSAE + f0 + tx];
    __syncthreads();
#pragma unroll
    for (int j = 0; j < 32; j += 8)
        g_WdecT[(size_t)(f0 + ty + j) * DMODEL + d0 + tx] = s[tx][ty + j];
}

// =====================================================================
// Kernel 3: per-token top-64 radix select (exact on our fp32 values,
// lowest-index tie-break) + ambiguity flagging
// =====================================================================
__device__ __forceinline__ unsigned int fkey(float x) {
    unsigned int u = __float_as_uint(x);
    unsigned int m = ((unsigned int)((int)u >> 31)) | 0x80000000u;
    return u ^ m;
}
__device__ __forceinline__ float keyval(unsigned int k) {
    unsigned int u = (k & 0x80000000u) ? (k ^ 0x80000000u) : ~k;
    return __uint_as_float(u);
}

__global__ __launch_bounds__(256)
void topk_select(const float* __restrict__ pre, float* __restrict__ sparse)
{
    extern __shared__ float srow[];
    __shared__ unsigned int hist[8][256];
    __shared__ unsigned int bitmap[DSAE / 32];
    __shared__ int s_gt[256], s_eq[256], s_base[256], s_ebase[256];
    __shared__ unsigned int sh_pfx;
    __shared__ int sh_need;
    __shared__ int s_flag;

    const int token = blockIdx.x;
    const int tid = threadIdx.x;
    const int wid = tid >> 5;
    const float* prow = pre + (size_t)token * DSAE;

    for (int i = tid; i < DSAE; i += 256) srow[i] = prow[i];
    __syncthreads();

    unsigned int pfx = 0;
    int need = KSP;
    for (int b = 3; b >= 0; --b) {
        for (int i = tid; i < 8 * 256; i += 256) ((unsigned int*)hist)[i] = 0;
        __syncthreads();
        const int sh = b * 8;
        for (int i = tid; i < DSAE; i += 256) {
            unsigned int k = fkey(srow[i]);
            bool m = (b == 3) || ((k >> (sh + 8)) == pfx);
            if (m) atomicAdd(&hist[wid][(k >> sh) & 255], 1u);
        }
        __syncthreads();
        if (tid < 256) {
            unsigned int s = 0;
#pragma unroll
            for (int w = 0; w < 8; w++) s += hist[w][tid];
            hist[0][tid] = s;
        }
        __syncthreads();
        if (tid == 0) {
            int cum = 0, v = 255;
            for (; v > 0; --v) {
                int c = (int)hist[0][v];
                if (cum + c >= need) break;
                cum += c;
            }
            sh_pfx = (pfx << 8) | (unsigned int)v;
            sh_need = need - cum;
        }
        __syncthreads();
        pfx = sh_pfx;
        need = sh_need;
        __syncthreads();
    }
    const unsigned int T = pfx;
    const int r = need;
    const float vT = keyval(T);

    const int seg = tid * 64;
    {
        int ngt = 0, neq = 0;
#pragma unroll 4
        for (int ii = 0; ii < 64; ii++) {
            unsigned int k = fkey(srow[seg + ii]);
            ngt += (k > T);
            neq += (k == T);
        }
        s_gt[tid] = ngt;
        s_eq[tid] = neq;
    }
    if (tid == 0) s_flag = 0;
    __syncthreads();
    if (tid == 0) {
        int eacc = 0, sacc = 0;
        for (int q = 0; q < 256; q++) {
            s_ebase[q] = eacc;
            int etake = r - eacc;
            if (etake < 0) etake = 0;
            if (etake > s_eq[q]) etake = s_eq[q];
            s_base[q] = sacc;
            sacc += s_gt[q] + etake;
            eacc += s_eq[q];
        }
    }
    __syncthreads();

    {
        unsigned int bits0 = 0, bits1 = 0;
        int p = s_base[tid];
        int e = s_ebase[tid];
        int*   oidx = g_topidx + (size_t)token * KSP;
        float* oval = g_topval + (size_t)token * KSP;
        for (int ii = 0; ii < 64; ii++) {
            int i = seg + ii;
            float x = srow[i];
            unsigned int k = fkey(x);
            bool gt = (k > T);
            bool eq = (k == T);
            bool take = gt || (eq && e < r);
            if (eq) e++;
            if (take) {
                oidx[p] = i;
                oval[p] = x;
                if (ii < 32) bits0 |= (1u << ii);
                else         bits1 |= (1u << (ii - 32));
                p++;
            }
        }
        bitmap[tid * 2]     = bits0;
        bitmap[tid * 2 + 1] = bits1;
    }
    __syncthreads();

    float* srow_out = sparse + (size_t)token * DSAE;
    for (int i = tid; i < DSAE; i += 256) {
        bool sel = (bitmap[i >> 5] >> (i & 31)) & 1u;
        float v = srow[i];
        srow_out[i] = sel ? v : 0.0f;
        if (!sel && fabsf(v - vT) <= BAND_EPS) s_flag = 1;
    }
    __syncthreads();
    if (tid == 0) {
        g_vT[token] = vT;
        g_flag[token] = s_flag;
    }
}

// =====================================================================
// Kernel 3b: exact fp64 boundary refinement for flagged tokens
// =====================================================================
__global__ __launch_bounds__(256)
void refine(const float* __restrict__ pre,
            const float* __restrict__ x,
            const float* __restrict__ Wenc,
            float* __restrict__ sparse)
{
    extern __shared__ float srow[];
    __shared__ int    s_band[64];
    __shared__ float  s_ef[64];
    __shared__ double s_red[256];
    __shared__ unsigned int bm[DSAE / 32];
    __shared__ int s_cnt[256], s_base[256];
    __shared__ int s_chosen[64];
    __shared__ int s_nin, s_c, s_nch;

    const int token = blockIdx.x;
    if (!g_flag[token]) return;

    const int tid = threadIdx.x;
    const float vT = g_vT[token];
    const float* prow = pre + (size_t)token * DSAE;

    for (int i = tid; i < DSAE; i += 256) srow[i] = prow[i];
    if (tid == 0) { s_nin = 0; s_c = 0; }
    __syncthreads();

    int nin_local = 0;
    for (int i = tid; i < DSAE; i += 256) {
        float v = srow[i];
        if (v > vT + BAND_EPS) {
            nin_local++;
        } else if (fabsf(v - vT) <= BAND_EPS) {
            int p = atomicAdd(&s_c, 1);
            if (p < 64) s_band[p] = i;
        }
    }
    atomicAdd(&s_nin, nin_local);
    __syncthreads();

    const int c = min(s_c, 64);
    const int need = KSP - s_nin;

    if (tid == 0) {
        for (int a = 1; a < c; a++) {
            int key = s_band[a], b = a - 1;
            for (; b >= 0 && s_band[b] > key; b--) s_band[b + 1] = s_band[b];
            s_band[b + 1] = key;
        }
    }
    __syncthreads();

    const float* xr = x + (size_t)token * DMODEL;
    for (int j = 0; j < c; j++) {
        const float* wr = Wenc + (size_t)s_band[j] * DMODEL;
        double p = 0.0;
        for (int d = tid; d < DMODEL; d += 256)
            p += (double)xr[d] * (double)wr[d];
        s_red[tid] = p;
        __syncthreads();
        for (int off = 128; off > 0; off >>= 1) {
            if (tid < off) s_red[tid] += s_red[tid + off];
            __syncthreads();
        }
        if (tid == 0) s_ef[j] = (float)s_red[0];
        __syncthreads();
    }

    if (tid == 0) {
        bool used[64];
        for (int j = 0; j < c; j++) used[j] = false;
        int nc = 0;
        for (int t = 0; t < need && t < c; t++) {
            int best = -1;
            for (int j = 0; j < c; j++)
                if (!used[j] && (best < 0 || s_ef[j] > s_ef[best])) best = j;
            used[best] = true;
            s_chosen[nc++] = s_band[best];
        }
        s_nch = nc;
    }
    __syncthreads();

    {
        int seg = tid * 64;
        unsigned int b0 = 0, b1 = 0;
        for (int ii = 0; ii < 64; ii++) {
            float v = srow[seg + ii];
            if (v > vT + BAND_EPS) {
                if (ii < 32) b0 |= (1u << ii);
                else         b1 |= (1u << (ii - 32));
            }
        }
        bm[tid * 2]     = b0;
        bm[tid * 2 + 1] = b1;
    }
    __syncthreads();
    if (tid == 0)
        for (int t = 0; t < s_nch; t++) {
            int i = s_chosen[t];
            bm[i >> 5] |= (1u << (i & 31));
        }
    __syncthreads();

    s_cnt[tid] = __popc(bm[tid * 2]) + __popc(bm[tid * 2 + 1]);
    __syncthreads();
    if (tid == 0) {
        int acc = 0;
        for (int q = 0; q < 256; q++) { s_base[q] = acc; acc += s_cnt[q]; }
    }
    __syncthreads();

    float* srow_out = sparse + (size_t)token * DSAE;
    int*   oidx = g_topidx + (size_t)token * KSP;
    float* oval = g_topval + (size_t)token * KSP;
    {
        int seg = tid * 64;
        int p = s_base[tid];
        for (int ii = 0; ii < 64; ii++) {
            int i = seg + ii;
            bool sel = (bm[i >> 5] >> (i & 31)) & 1u;
            srow_out[i] = sel ? srow[i] : 0.0f;
            if (sel) { oidx[p] = i; oval[p] = srow[i]; p++; }
        }
    }
}

// =====================================================================
// Kernel 4: sparse decoder
// =====================================================================
__global__ __launch_bounds__(256)
void sparse_decode(const float* __restrict__ bdec,
                   float* __restrict__ recon)
{
    const int token = blockIdx.x;
    const int chunk = blockIdx.y * 1024;
    const int t = threadIdx.x;

    __shared__ int   fi[KSP];
    __shared__ float fv[KSP];
    if (t < KSP) {
        fi[t] = g_topidx[(size_t)token * KSP + t];
        fv[t] = g_topval[(size_t)token * KSP + t];
    }
    __syncthreads();

    float a0 = bdec[chunk + t];
    float a1 = bdec[chunk + 256 + t];
    float a2 = bdec[chunk + 512 + t];
    float a3 = bdec[chunk + 768 + t];

#pragma unroll 4
    for (int j = 0; j < KSP; j++) {
        const float* w = g_WdecT + (size_t)fi[j] * DMODEL + chunk;
        float v = fv[j];
        a0 = fmaf(v, w[t], a0);
        a1 = fmaf(v, w[256 + t], a1);
        a2 = fmaf(v, w[512 + t], a2);
        a3 = fmaf(v, w[768 + t], a3);
    }

    float* o = recon + (size_t)token * DMODEL + chunk;
    o[t]       = a0;
    o[256 + t] = a1;
    o[512 + t] = a2;
    o[768 + t] = a3;
}

// =====================================================================
// launch
// =====================================================================
extern "C" void kernel_launch(void* const* d_in, const int* in_sizes, int n_in,
                              void* d_out, int out_size)
{
    const float* x     = (const float*)d_in[0];
    const float* W_enc = (const float*)d_in[1];
    const float* b_enc = (const float*)d_in[2];
    const float* W_dec = (const float*)d_in[3];
    const float* b_dec = (const float*)d_in[4];

    float* out    = (float*)d_out;
    float* recon  = out;
    float* sparse = out + (size_t)NTOK * DMODEL;
    float* pre    = sparse + (size_t)NTOK * DSAE;

    cudaFuncSetAttribute(topk_select, cudaFuncAttributeMaxDynamicSharedMemorySize,
                         DSAE * (int)sizeof(float));
    cudaFuncSetAttribute(refine, cudaFuncAttributeMaxDynamicSharedMemorySize,
                         DSAE * (int)sizeof(float));
    cudaFuncSetAttribute(enc_hmma, cudaFuncAttributeMaxDynamicSharedMemorySize,
                         HB_SMEM);

    __nv_bfloat16 *Ahi, *Amid, *Bhi, *Bmid;
    cudaGetSymbolAddress((void**)&Ahi,  g_Ahi);
    cudaGetSymbolAddress((void**)&Amid, g_Amid);
    cudaGetSymbolAddress((void**)&Bhi,  g_Bhi);
    cudaGetSymbolAddress((void**)&Bmid, g_Bmid);

    // bf16 splits of x and W_enc (vectorized)
    split_pair<<<2048, 256>>>((const float4*)x, (uint2*)Ahi, (uint2*)Amid,
                              (size_t)NTOK * DMODEL / 4);
    split_pair<<<4096, 256>>>((const float4*)W_enc, (uint2*)Bhi, (uint2*)Bmid,
                              (size_t)DSAE * DMODEL / 4);

    // HMMA encoder GEMM -> pre_acts (+bias), 64x64 warp tiles + ldmatrix
    enc_hmma<<<(NTOK / HB_BM) * (DSAE / HB_BN), 256, HB_SMEM>>>(b_enc, pre);

    // transpose decoder weights
    wdec_transpose<<<dim3(DSAE / 32, DMODEL / 32), dim3(32, 8)>>>(W_dec);

    // per-token top-64 -> sparse_acts + compacted lists + ambiguity flags
    topk_select<<<NTOK, 256, DSAE * sizeof(float)>>>(pre, sparse);

    // exact fp64 boundary refinement
    refine<<<NTOK, 256, DSAE * sizeof(float)>>>(pre, x, W_enc, sparse);

    // sparse decode -> reconstruction
    sparse_decode<<<dim3(NTOK, DMODEL / 1024), 256>>>(b_dec, recon);
}

// round 12
// speedup vs baseline: 1.0970x; 1.0970x over previous
#include <cuda_runtime.h>
#include <cuda_bf16.h>
#include <cstdint>

// Problem constants
#define NTOK   8192
#define DMODEL 4096
#define DSAE   16384
#define KSP    64

#define BAND_EPS 2e-4f   // boundary-ambiguity band on pre_act value scale

// d_out layout: [recon (NTOK*DMODEL) | sparse (NTOK*DSAE) | pre (NTOK*DSAE)]

// ---------------- scratch (__device__ globals) ----------------
__device__ float g_WdecT[(size_t)DSAE * DMODEL];   // 256 MB transposed decoder weights
__device__ int   g_topidx[(size_t)NTOK * KSP];
__device__ float g_topval[(size_t)NTOK * KSP];
__device__ float g_vT[NTOK];
__device__ int   g_flag[NTOK];
// bf16 split operands for tensor-core encoder
__device__ __nv_bfloat16 g_Ahi[(size_t)NTOK * DMODEL];   // 64 MB
__device__ __nv_bfloat16 g_Amid[(size_t)NTOK * DMODEL];  // 64 MB
__device__ __nv_bfloat16 g_Bhi[(size_t)DSAE * DMODEL];   // 128 MB
__device__ __nv_bfloat16 g_Bmid[(size_t)DSAE * DMODEL];  // 128 MB

// ---------------- baseline-PTX helpers (sm_80-level only; NO _a features) -----
__device__ __forceinline__ uint32_t smem_to_u32(const void* p) {
    uint32_t a;
    asm("{ .reg .u64 t; cvta.to.shared.u64 t, %1; cvt.u32.u64 %0, t; }"
        : "=r"(a) : "l"(p));
    return a;
}
__device__ __forceinline__ void cp_async16(uint32_t saddr, const void* gaddr) {
    asm volatile("cp.async.cg.shared.global [%0], [%1], 16;" :: "r"(saddr), "l"(gaddr));
}
#define CP_COMMIT() asm volatile("cp.async.commit_group;" ::: "memory")
template <int N>
__device__ __forceinline__ void cp_wait_group() {
    asm volatile("cp.async.wait_group %0;" :: "n"(N) : "memory");
}

// mma.sync m16n8k16 row.col bf16 -> f32 (PTX ISA 7.0, baseline sm_80)
__device__ __forceinline__ void mma16816(float* d, const uint32_t* a, const uint32_t* b) {
    asm volatile(
        "mma.sync.aligned.m16n8k16.row.col.f32.bf16.bf16.f32 "
        "{%0,%1,%2,%3}, {%4,%5,%6,%7}, {%8,%9}, {%0,%1,%2,%3};"
        : "+f"(d[0]), "+f"(d[1]), "+f"(d[2]), "+f"(d[3])
        : "r"(a[0]), "r"(a[1]), "r"(a[2]), "r"(a[3]), "r"(b[0]), "r"(b[1]));
}

// =====================================================================
// Kernel 0: bf16 two-way split, vectorized (float4 in, bf16x2 packed out)
// =====================================================================
__global__ __launch_bounds__(256)
void split_pair(const float4* __restrict__ src, uint2* __restrict__ hi,
                uint2* __restrict__ mid, size_t n4)
{
    size_t i = (size_t)blockIdx.x * 256 + threadIdx.x;
    size_t stride = (size_t)gridDim.x * 256;
    for (; i < n4; i += stride) {
        float4 v = src[i];
        __nv_bfloat162 h01 = __float22bfloat162_rn(make_float2(v.x, v.y));
        __nv_bfloat162 h23 = __float22bfloat162_rn(make_float2(v.z, v.w));
        float2 hf01 = __bfloat1622float2(h01);
        float2 hf23 = __bfloat1622float2(h23);
        __nv_bfloat162 m01 = __float22bfloat162_rn(make_float2(v.x - hf01.x, v.y - hf01.y));
        __nv_bfloat162 m23 = __float22bfloat162_rn(make_float2(v.z - hf23.x, v.w - hf23.y));
        hi[i]  = make_uint2(*(uint32_t*)&h01, *(uint32_t*)&h23);
        mid[i] = make_uint2(*(uint32_t*)&m01, *(uint32_t*)&m23);
    }
}

// =====================================================================
// Kernel 1: HMMA encoder GEMM (bf16x3 split):
//   pre = Ahi·Bhi^T + Ahi·Bmid^T + Amid·Bhi^T + bias  (fp32 accum)
// CTA tile 128x256, BK=32, 3-stage cp.async pipeline, 256 threads,
// 64x64 warp tiles, LDS.32 fragment loads (R10 scheme — proven fastest).
// NEW vs R10: inner loop split into 3 term-passes so each accumulator's
// dependent MMAs are 32 instructions apart (hides HMMA latency). The
// per-accumulator contribution order (hh, hm, mh per k-step) is UNCHANGED
// -> pre_acts bitwise identical to R10/R11.
// =====================================================================
#define HB_BM 128
#define HB_BN 256
#define HB_BK 32
#define HB_RSB 80                        // 64B data (32 bf16) + 16B pad
#define HB_A_MAT (128 * HB_RSB)          // 10240 B
#define HB_B_MAT (256 * HB_RSB)          // 20480 B
#define HB_STAGE (2 * HB_A_MAT + 2 * HB_B_MAT)   // 61440 B
#define HB_NSTAGE 3
#define HB_SMEM (HB_NSTAGE * HB_STAGE)   // 184320 B
#define OFF_AHI  0
#define OFF_AMID HB_A_MAT
#define OFF_BHI  (2 * HB_A_MAT)
#define OFF_BMID (2 * HB_A_MAT + HB_B_MAT)

__global__ __launch_bounds__(256, 1)
void enc_hmma(const float* __restrict__ bias, float* __restrict__ C)
{
    extern __shared__ char smem[];
    const int tid  = threadIdx.x;
    const int wid  = tid >> 5;
    const int lane = tid & 31;

    // rasterize: groups of 8 M-tiles x all 64 N-tiles (A slice L2-resident)
    const int t  = blockIdx.x;
    const int g  = t >> 9;              // /(8*64)
    const int r  = t & 511;
    const int mt = (g << 3) + (r & 7);
    const int nt = r >> 3;
    const int m0 = mt * HB_BM;
    const int n0 = nt * HB_BN;

    const int warp_m = (wid >> 2) * 64;   // 0 / 64
    const int warp_n = (wid & 3) * 64;    // 0..192

    float acc[4][8][4];
#pragma unroll
    for (int i = 0; i < 4; i++)
#pragma unroll
        for (int j = 0; j < 8; j++)
#pragma unroll
            for (int q = 0; q < 4; q++) acc[i][j][q] = 0.0f;

    const uint32_t sb = smem_to_u32(smem);
    const int NCH = DMODEL / HB_BK;      // 128

    // ---- per-thread loader plan: 12 x 16B chunks per stage (3072 total) ----
    uint32_t soff[12];
    const char* gptr[12];
    {
        const char* gAhi  = (const char*)g_Ahi  + (size_t)m0 * DMODEL * 2;
        const char* gAmid = (const char*)g_Amid + (size_t)m0 * DMODEL * 2;
        const char* gBhi  = (const char*)g_Bhi  + (size_t)n0 * DMODEL * 2;
        const char* gBmid = (const char*)g_Bmid + (size_t)n0 * DMODEL * 2;
#pragma unroll
        for (int i = 0; i < 12; i++) {
            int c = tid + i * 256;
            if (c < 1024) {                       // A chunks: 2 mats x 128 rows x 4
                int mat = c >> 9;
                int row = (c >> 2) & 127;
                int col = c & 3;
                soff[i] = (mat ? OFF_AMID : OFF_AHI) + row * HB_RSB + col * 16;
                gptr[i] = (mat ? gAmid : gAhi) + (size_t)row * (DMODEL * 2) + col * 16;
            } else {                              // B chunks: 2 mats x 256 rows x 4
                int cb  = c - 1024;
                int mat = cb >> 10;
                int row = (cb >> 2) & 255;
                int col = cb & 3;
                soff[i] = (mat ? OFF_BMID : OFF_BHI) + row * HB_RSB + col * 16;
                gptr[i] = (mat ? gBmid : gBhi) + (size_t)row * (DMODEL * 2) + col * 16;
            }
        }
    }

    auto load_stage = [&](int ch, int s) {
        const uint32_t stg = sb + s * HB_STAGE;
        const size_t kadv = (size_t)ch * 64;     // 32 bf16 = 64 bytes per chunk
#pragma unroll
        for (int i = 0; i < 12; i++)
            cp_async16(stg + soff[i], gptr[i] + kadv);
        CP_COMMIT();
    };

    load_stage(0, 0);
    load_stage(1, 1);

    const int gg = lane >> 2;
    const int tg = lane & 3;

    for (int ch = 0; ch < NCH; ch++) {
        if (ch + 1 < NCH) cp_wait_group<1>();
        else              cp_wait_group<0>();
        __syncthreads();

        if (ch + 2 < NCH) load_stage(ch + 2, (ch + 2) % 3);

        const char* stg = smem + (ch % 3) * HB_STAGE;

#pragma unroll
        for (int ks = 0; ks < 2; ks++) {
            const int kb = ks * 32;              // 16 bf16 = 32B per k-step
            uint32_t ah[4][4], am[4][4], bh[8][2], bm[8][2];
#pragma unroll
            for (int i = 0; i < 4; i++) {
                const char* pa = stg + OFF_AHI +
                                 (warp_m + i * 16 + gg) * HB_RSB + kb + tg * 4;
                ah[i][0] = *(const uint32_t*)pa;
                ah[i][1] = *(const uint32_t*)(pa + 8 * HB_RSB);
                ah[i][2] = *(const uint32_t*)(pa + 16);
                ah[i][3] = *(const uint32_t*)(pa + 8 * HB_RSB + 16);
                const char* pm = pa + (OFF_AMID - OFF_AHI);
                am[i][0] = *(const uint32_t*)pm;
                am[i][1] = *(const uint32_t*)(pm + 8 * HB_RSB);
                am[i][2] = *(const uint32_t*)(pm + 16);
                am[i][3] = *(const uint32_t*)(pm + 8 * HB_RSB + 16);
            }
#pragma unroll
            for (int j = 0; j < 8; j++) {
                const char* pb = stg + OFF_BHI +
                                 (warp_n + j * 8 + gg) * HB_RSB + kb + tg * 4;
                bh[j][0] = *(const uint32_t*)pb;
                bh[j][1] = *(const uint32_t*)(pb + 16);
                const char* pb2 = pb + (OFF_BMID - OFF_BHI);
                bm[j][0] = *(const uint32_t*)pb2;
                bm[j][1] = *(const uint32_t*)(pb2 + 16);
            }
            // pass 1: all hi·hi (32 independent MMAs)
#pragma unroll
            for (int j = 0; j < 8; j++)
#pragma unroll
                for (int i = 0; i < 4; i++)
                    mma16816(acc[i][j], ah[i], bh[j]);
            // pass 2: all hi·mid
#pragma unroll
            for (int j = 0; j < 8; j++)
#pragma unroll
                for (int i = 0; i < 4; i++)
                    mma16816(acc[i][j], ah[i], bm[j]);
            // pass 3: all mid·hi
#pragma unroll
            for (int j = 0; j < 8; j++)
#pragma unroll
                for (int i = 0; i < 4; i++)
                    mma16816(acc[i][j], am[i], bh[j]);
        }
    }

    // ---- epilogue: bias add + store ----
#pragma unroll
    for (int i = 0; i < 4; i++) {
        const int row0 = m0 + warp_m + i * 16 + gg;
#pragma unroll
        for (int j = 0; j < 8; j++) {
            const int col = n0 + warp_n + j * 8 + tg * 2;
            const float b0 = bias[col];
            const float b1 = bias[col + 1];
            float* p0 = C + (size_t)row0 * DSAE + col;
            float* p1 = C + (size_t)(row0 + 8) * DSAE + col;
            *(float2*)p0 = make_float2(acc[i][j][0] + b0, acc[i][j][1] + b1);
            *(float2*)p1 = make_float2(acc[i][j][2] + b0, acc[i][j][3] + b1);
        }
    }
}

// =====================================================================
// Kernel 2: transpose W_dec (DMODEL x DSAE) -> g_WdecT (DSAE x DMODEL)
// =====================================================================
__global__ __launch_bounds__(256)
void wdec_transpose(const float* __restrict__ W)
{
    __shared__ float s[32][33];
    const int f0 = blockIdx.x * 32;
    const int d0 = blockIdx.y * 32;
    const int tx = threadIdx.x;
    const int ty = threadIdx.y;
#pragma unroll
    for (int j = 0; j < 32; j += 8)
        s[ty + j][tx] = W[(size_t)(d0 + ty + j) * DSAE + f0 + tx];
    __syncthreads();
#pragma unroll
    for (int j = 0; j < 32; j += 8)
        g_WdecT[(size_t)(f0 + ty + j) * DMODEL + d0 + tx] = s[tx][ty + j];
}

// =====================================================================
// Kernel 3: per-token top-64 radix select (exact on our fp32 values,
// lowest-index tie-break) + ambiguity flagging
// =====================================================================
__device__ __forceinline__ unsigned int fkey(float x) {
    unsigned int u = __float_as_uint(x);
    unsigned int m = ((unsigned int)((int)u >> 31)) | 0x80000000u;
    return u ^ m;
}
__device__ __forceinline__ float keyval(unsigned int k) {
    unsigned int u = (k & 0x80000000u) ? (k ^ 0x80000000u) : ~k;
    return __uint_as_float(u);
}

__global__ __launch_bounds__(256)
void topk_select(const float* __restrict__ pre, float* __restrict__ sparse)
{
    extern __shared__ float srow[];
    __shared__ unsigned int hist[8][256];
    __shared__ unsigned int bitmap[DSAE / 32];
    __shared__ int s_gt[256], s_eq[256], s_base[256], s_ebase[256];
    __shared__ unsigned int sh_pfx;
    __shared__ int sh_need;
    __shared__ int s_flag;

    const int token = blockIdx.x;
    const int tid = threadIdx.x;
    const int wid = tid >> 5;
    const float* prow = pre + (size_t)token * DSAE;

    for (int i = tid; i < DSAE; i += 256) srow[i] = prow[i];
    __syncthreads();

    unsigned int pfx = 0;
    int need = KSP;
    for (int b = 3; b >= 0; --b) {
        for (int i = tid; i < 8 * 256; i += 256) ((unsigned int*)hist)[i] = 0;
        __syncthreads();
        const int sh = b * 8;
        for (int i = tid; i < DSAE; i += 256) {
            unsigned int k = fkey(srow[i]);
            bool m = (b == 3) || ((k >> (sh + 8)) == pfx);
            if (m) atomicAdd(&hist[wid][(k >> sh) & 255], 1u);
        }
        __syncthreads();
        if (tid < 256) {
            unsigned int s = 0;
#pragma unroll
            for (int w = 0; w < 8; w++) s += hist[w][tid];
            hist[0][tid] = s;
        }
        __syncthreads();
        if (tid == 0) {
            int cum = 0, v = 255;
            for (; v > 0; --v) {
                int c = (int)hist[0][v];
                if (cum + c >= need) break;
                cum += c;
            }
            sh_pfx = (pfx << 8) | (unsigned int)v;
            sh_need = need - cum;
        }
        __syncthreads();
        pfx = sh_pfx;
        need = sh_need;
        __syncthreads();
    }
    const unsigned int T = pfx;
    const int r = need;
    const float vT = keyval(T);

    const int seg = tid * 64;
    {
        int ngt = 0, neq = 0;
#pragma unroll 4
        for (int ii = 0; ii < 64; ii++) {
            unsigned int k = fkey(srow[seg + ii]);
            ngt += (k > T);
            neq += (k == T);
        }
        s_gt[tid] = ngt;
        s_eq[tid] = neq;
    }
    if (tid == 0) s_flag = 0;
    __syncthreads();
    if (tid == 0) {
        int eacc = 0, sacc = 0;
        for (int q = 0; q < 256; q++) {
            s_ebase[q] = eacc;
            int etake = r - eacc;
            if (etake < 0) etake = 0;
            if (etake > s_eq[q]) etake = s_eq[q];
            s_base[q] = sacc;
            sacc += s_gt[q] + etake;
            eacc += s_eq[q];
        }
    }
    __syncthreads();

    {
        unsigned int bits0 = 0, bits1 = 0;
        int p = s_base[tid];
        int e = s_ebase[tid];
        int*   oidx = g_topidx + (size_t)token * KSP;
        float* oval = g_topval + (size_t)token * KSP;
        for (int ii = 0; ii < 64; ii++) {
            int i = seg + ii;
            float x = srow[i];
            unsigned int k = fkey(x);
            bool gt = (k > T);
            bool eq = (k == T);
            bool take = gt || (eq && e < r);
            if (eq) e++;
            if (take) {
                oidx[p] = i;
                oval[p] = x;
                if (ii < 32) bits0 |= (1u << ii);
                else         bits1 |= (1u << (ii - 32));
                p++;
            }
        }
        bitmap[tid * 2]     = bits0;
        bitmap[tid * 2 + 1] = bits1;
    }
    __syncthreads();

    float* srow_out = sparse + (size_t)token * DSAE;
    for (int i = tid; i < DSAE; i += 256) {
        bool sel = (bitmap[i >> 5] >> (i & 31)) & 1u;
        float v = srow[i];
        srow_out[i] = sel ? v : 0.0f;
        if (!sel && fabsf(v - vT) <= BAND_EPS) s_flag = 1;
    }
    __syncthreads();
    if (tid == 0) {
        g_vT[token] = vT;
        g_flag[token] = s_flag;
    }
}

// =====================================================================
// Kernel 3b: exact fp64 boundary refinement for flagged tokens
// =====================================================================
__global__ __launch_bounds__(256)
void refine(const float* __restrict__ pre,
            const float* __restrict__ x,
            const float* __restrict__ Wenc,
            float* __restrict__ sparse)
{
    extern __shared__ float srow[];
    __shared__ int    s_band[64];
    __shared__ float  s_ef[64];
    __shared__ double s_red[256];
    __shared__ unsigned int bm[DSAE / 32];
    __shared__ int s_cnt[256], s_base[256];
    __shared__ int s_chosen[64];
    __shared__ int s_nin, s_c, s_nch;

    const int token = blockIdx.x;
    if (!g_flag[token]) return;

    const int tid = threadIdx.x;
    const float vT = g_vT[token];
    const float* prow = pre + (size_t)token * DSAE;

    for (int i = tid; i < DSAE; i += 256) srow[i] = prow[i];
    if (tid == 0) { s_nin = 0; s_c = 0; }
    __syncthreads();

    int nin_local = 0;
    for (int i = tid; i < DSAE; i += 256) {
        float v = srow[i];
        if (v > vT + BAND_EPS) {
            nin_local++;
        } else if (fabsf(v - vT) <= BAND_EPS) {
            int p = atomicAdd(&s_c, 1);
            if (p < 64) s_band[p] = i;
        }
    }
    atomicAdd(&s_nin, nin_local);
    __syncthreads();

    const int c = min(s_c, 64);
    const int need = KSP - s_nin;

    if (tid == 0) {
        for (int a = 1; a < c; a++) {
            int key = s_band[a], b = a - 1;
            for (; b >= 0 && s_band[b] > key; b--) s_band[b + 1] = s_band[b];
            s_band[b + 1] = key;
        }
    }
    __syncthreads();

    const float* xr = x + (size_t)token * DMODEL;
    for (int j = 0; j < c; j++) {
        const float* wr = Wenc + (size_t)s_band[j] * DMODEL;
        double p = 0.0;
        for (int d = tid; d < DMODEL; d += 256)
            p += (double)xr[d] * (double)wr[d];
        s_red[tid] = p;
        __syncthreads();
        for (int off = 128; off > 0; off >>= 1) {
            if (tid < off) s_red[tid] += s_red[tid + off];
            __syncthreads();
        }
        if (tid == 0) s_ef[j] = (float)s_red[0];
        __syncthreads();
    }

    if (tid == 0) {
        bool used[64];
        for (int j = 0; j < c; j++) used[j] = false;
        int nc = 0;
        for (int t = 0; t < need && t < c; t++) {
            int best = -1;
            for (int j = 0; j < c; j++)
                if (!used[j] && (best < 0 || s_ef[j] > s_ef[best])) best = j;
            used[best] = true;
            s_chosen[nc++] = s_band[best];
        }
        s_nch = nc;
    }
    __syncthreads();

    {
        int seg = tid * 64;
        unsigned int b0 = 0, b1 = 0;
        for (int ii = 0; ii < 64; ii++) {
            float v = srow[seg + ii];
            if (v > vT + BAND_EPS) {
                if (ii < 32) b0 |= (1u << ii);
                else         b1 |= (1u << (ii - 32));
            }
        }
        bm[tid * 2]     = b0;
        bm[tid * 2 + 1] = b1;
    }
    __syncthreads();
    if (tid == 0)
        for (int t = 0; t < s_nch; t++) {
            int i = s_chosen[t];
            bm[i >> 5] |= (1u << (i & 31));
        }
    __syncthreads();

    s_cnt[tid] = __popc(bm[tid * 2]) + __popc(bm[tid * 2 + 1]);
    __syncthreads();
    if (tid == 0) {
        int acc = 0;
        for (int q = 0; q < 256; q++) { s_base[q] = acc; acc += s_cnt[q]; }
    }
    __syncthreads();

    float* srow_out = sparse + (size_t)token * DSAE;
    int*   oidx = g_topidx + (size_t)token * KSP;
    float* oval = g_topval + (size_t)token * KSP;
    {
        int seg = tid * 64;
        int p = s_base[tid];
        for (int ii = 0; ii < 64; ii++) {
            int i = seg + ii;
            bool sel = (bm[i >> 5] >> (i & 31)) & 1u;
            srow_out[i] = sel ? srow[i] : 0.0f;
            if (sel) { oidx[p] = i; oval[p] = srow[i]; p++; }
        }
    }
}

// =====================================================================
// Kernel 4: sparse decoder
// =====================================================================
__global__ __launch_bounds__(256)
void sparse_decode(const float* __restrict__ bdec,
                   float* __restrict__ recon)
{
    const int token = blockIdx.x;
    const int chunk = blockIdx.y * 1024;
    const int t = threadIdx.x;

    __shared__ int   fi[KSP];
    __shared__ float fv[KSP];
    if (t < KSP) {
        fi[t] = g_topidx[(size_t)token * KSP + t];
        fv[t] = g_topval[(size_t)token * KSP + t];
    }
    __syncthreads();

    float a0 = bdec[chunk + t];
    float a1 = bdec[chunk + 256 + t];
    float a2 = bdec[chunk + 512 + t];
    float a3 = bdec[chunk + 768 + t];

#pragma unroll 4
    for (int j = 0; j < KSP; j++) {
        const float* w = g_WdecT + (size_t)fi[j] * DMODEL + chunk;
        float v = fv[j];
        a0 = fmaf(v, w[t], a0);
        a1 = fmaf(v, w[256 + t], a1);
        a2 = fmaf(v, w[512 + t], a2);
        a3 = fmaf(v, w[768 + t], a3);
    }

    float* o = recon + (size_t)token * DMODEL + chunk;
    o[t]       = a0;
    o[256 + t] = a1;
    o[512 + t] = a2;
    o[768 + t] = a3;
}

// =====================================================================
// launch
// =====================================================================
extern "C" void kernel_launch(void* const* d_in, const int* in_sizes, int n_in,
                              void* d_out, int out_size)
{
    const float* x     = (const float*)d_in[0];
    const float* W_enc = (const float*)d_in[1];
    const float* b_enc = (const float*)d_in[2];
    const float* W_dec = (const float*)d_in[3];
    const float* b_dec = (const float*)d_in[4];

    float* out    = (float*)d_out;
    float* recon  = out;
    float* sparse = out + (size_t)NTOK * DMODEL;
    float* pre    = sparse + (size_t)NTOK * DSAE;

    cudaFuncSetAttribute(topk_select, cudaFuncAttributeMaxDynamicSharedMemorySize,
                         DSAE * (int)sizeof(float));
    cudaFuncSetAttribute(refine, cudaFuncAttributeMaxDynamicSharedMemorySize,
                         DSAE * (int)sizeof(float));
    cudaFuncSetAttribute(enc_hmma, cudaFuncAttributeMaxDynamicSharedMemorySize,
                         HB_SMEM);

    __nv_bfloat16 *Ahi, *Amid, *Bhi, *Bmid;
    cudaGetSymbolAddress((void**)&Ahi,  g_Ahi);
    cudaGetSymbolAddress((void**)&Amid, g_Amid);
    cudaGetSymbolAddress((void**)&Bhi,  g_Bhi);
    cudaGetSymbolAddress((void**)&Bmid, g_Bmid);

    // bf16 splits of x and W_enc (vectorized)
    split_pair<<<2048, 256>>>((const float4*)x, (uint2*)Ahi, (uint2*)Amid,
                              (size_t)NTOK * DMODEL / 4);
    split_pair<<<4096, 256>>>((const float4*)W_enc, (uint2*)Bhi, (uint2*)Bmid,
                              (size_t)DSAE * DMODEL / 4);

    // HMMA encoder GEMM -> pre_acts (+bias), 3-pass MMA ordering
    enc_hmma<<<(NTOK / HB_BM) * (DSAE / HB_BN), 256, HB_SMEM>>>(b_enc, pre);

    // transpose decoder weights
    wdec_transpose<<<dim3(DSAE / 32, DMODEL / 32), dim3(32, 8)>>>(W_dec);

    // per-token top-64 -> sparse_acts + compacted lists + ambiguity flags
    topk_select<<<NTOK, 256, DSAE * sizeof(float)>>>(pre, sparse);

    // exact fp64 boundary refinement
    refine<<<NTOK, 256, DSAE * sizeof(float)>>>(pre, x, W_enc, sparse);

    // sparse decode -> reconstruction
    sparse_decode<<<dim3(NTOK, DMODEL / 1024), 256>>>(b_dec, recon);
}